// round 14
// baseline (speedup 1.0000x reference)
#include <cuda_runtime.h>
#include <cuda_fp16.h>

#define BB 2
#define NN 16384
#define KT 58
#define DD 64
#define ROWS (BB*NN)          // 32768
#define NITER 10
#define STRIDE 160            // padded slots per destination row
#define PROP_BLOCKS 888       // 148 SMs x 6 resident blocks

// ---- static device scratch (no runtime allocs; zero-initialized at load) ----
__device__ __half2  g_hh[2][ROWS * 32];       // ping-pong h, fp16, 4 MB each
__device__ int      g_cnt[ROWS];              // fill cursor; ALWAYS left zeroed by k_pad
__device__ int      g_deg[ROWS];              // padded degree consumed by k_prop
__device__ int      g_work[NITER];            // per-iteration work-steal cursors
__device__ unsigned g_edges[ROWS * STRIDE];   // packed {src:16 | fp16(w):16}, 21 MB

static __device__ __forceinline__ unsigned h2_bits(__half2 h) {
    return *reinterpret_cast<unsigned*>(&h);
}
// duplicate the high 16 bits (fp16 weight) into both halves -> half2(w, w)
static __device__ __forceinline__ __half2 dup_hi(unsigned e) {
    unsigned d;
    asm("prmt.b32 %0, %1, %1, 0x3232;" : "=r"(d) : "r"(e));
    return *reinterpret_cast<__half2*>(&d);
}

// Fused prologue: per-row softmax(h0) -> g_hh[0], and adjacency+transposed fill.
// Relies on g_cnt == 0 on entry (static init on first run; k_pad re-zeroes after).
__global__ void k_fused(const float* __restrict__ h0,
                        const float* __restrict__ logits,
                        const int*   __restrict__ vind) {
    int wid  = (blockIdx.x * blockDim.x + threadIdx.x) >> 5;
    int lane = threadIdx.x & 31;
    if (wid >= ROWS) return;

    // ---- part 1: h = softmax(h0) over D=64, stored fp16 ----
    {
        const float2* r = (const float2*)(h0 + (size_t)wid * DD);
        float2 v = r[lane];
        float m = fmaxf(v.x, v.y);
        #pragma unroll
        for (int o = 16; o; o >>= 1) m = fmaxf(m, __shfl_xor_sync(0xffffffffu, m, o));
        float ea = __expf(v.x - m), eb = __expf(v.y - m);
        float s = ea + eb;
        #pragma unroll
        for (int o = 16; o; o >>= 1) s += __shfl_xor_sync(0xffffffffu, s, o);
        float inv = 1.0f / s;
        g_hh[0][(size_t)wid * 32 + lane] = __floats2half2_rn(ea * inv, eb * inv);
    }

    // ---- part 2: w = exp(l - rowmax) (== softmax/max(softmax)); transposed fill ----
    const float* r = logits + (size_t)wid * KT;
    float a = r[lane];
    float b = (lane < KT - 32) ? r[lane + 32] : -3.0e38f;
    float m = fmaxf(a, b);
    #pragma unroll
    for (int o = 16; o; o >>= 1) m = fmaxf(m, __shfl_xor_sync(0xffffffffu, m, o));
    int batch = wid / NN;
    int u     = wid - batch * NN;
    const int* vr = vind + (size_t)wid * KT;
    {
        int v = vr[lane];
        if ((unsigned)v < NN) {
            int gv = batch * NN + v;
            int p = atomicAdd(&g_cnt[gv], 1);
            unsigned wb = (unsigned)__half_as_ushort(__float2half_rn(__expf(a - m)));
            if (p < STRIDE)
                g_edges[(size_t)gv * STRIDE + p] = (unsigned)u | (wb << 16);
        }
    }
    if (lane < KT - 32) {
        int v = vr[lane + 32];
        if ((unsigned)v < NN) {
            int gv = batch * NN + v;
            int p = atomicAdd(&g_cnt[gv], 1);
            unsigned wb = (unsigned)__half_as_ushort(__float2half_rn(__expf(b - m)));
            if (p < STRIDE)
                g_edges[(size_t)gv * STRIDE + p] = (unsigned)u | (wb << 16);
        }
    }
}

// Pad each row's edge list to a multiple of 4 with zero edges, publish padded degree
// to g_deg, re-zero g_cnt and the per-iteration work-steal cursors so every
// graph replay starts clean.
__global__ void k_pad() {
    int i = blockIdx.x * blockDim.x + threadIdx.x;
    if (i < NITER) g_work[i] = 0;
    if (i >= ROWS) return;
    int c = g_cnt[i];
    if (c > STRIDE) c = STRIDE;
    int np = (c + 3) & ~3;
    unsigned* e = g_edges + (size_t)i * STRIDE;
    for (int p = c; p < np; p++) e[p] = 0u;
    g_deg[i] = np;
    g_cnt[i] = 0;
}

// One propagation step: out[v] = L2norm( sum_e w_e * h[u_e] ).
// Work-stealing: each warp pulls destination rows from g_work[it] (~4.6 rows/warp)
// to smooth Poisson degree imbalance and the wave tail.
// Per row: 8 lanes per edge (octet = lane>>3 picks edge q*4+oct), lane covers 8 dims
// [(lane&7)*8..+8) via one 16B LDG.128 + 4 HFMA2. 16 edges per fp32 spill.
// NOTE: min-blocks hint 6 => 40 regs. 7 forces 32 regs -> h-load MLP collapse (1.4x slower).
template <bool LAST>
__global__ void __launch_bounds__(256, 6)
k_prop(const __half2* __restrict__ hin, __half2* __restrict__ hout,
       float* __restrict__ fout, int it) {
    int lane  = threadIdx.x & 31;
    int oct   = lane >> 3;     // which of 4 concurrent edges in a quad
    int chunk = lane & 7;      // which 16B slice of the 128B h row

    for (;;) {
        int wid;
        if (lane == 0) wid = atomicAdd(&g_work[it], 1);
        wid = __shfl_sync(0xffffffffu, wid, 0);
        if (wid >= ROWS) return;

        int batch = wid / NN;
        const char*     hlane = (const char*)(hin + (size_t)batch * NN * 32) + chunk * 16;
        const unsigned* eb    = g_edges + (size_t)wid * STRIDE + oct;

        int nq  = g_deg[wid] >> 2;     // quads (degree is a multiple of 4)
        int nq4 = nq & ~3;             // full 16-edge super-groups

        float f0 = 0.f, f1 = 0.f, f2 = 0.f, f3 = 0.f, f4 = 0.f, f5 = 0.f, f6 = 0.f, f7 = 0.f;

        int q = 0;
        for (; q < nq4; q += 4) {
            __half2 ha0 = __float2half2_rn(0.f), ha1 = ha0, ha2 = ha0, ha3 = ha0;
            #pragma unroll
            for (int k = 0; k < 4; k++) {
                unsigned e = eb[(q + k) * 4];
                __half2 ww = dup_hi(e);
                uint4 hv = *(const uint4*)(hlane + (size_t)(e & 0xFFFFu) * 128);
                ha0 = __hfma2(ww, *reinterpret_cast<__half2*>(&hv.x), ha0);
                ha1 = __hfma2(ww, *reinterpret_cast<__half2*>(&hv.y), ha1);
                ha2 = __hfma2(ww, *reinterpret_cast<__half2*>(&hv.z), ha2);
                ha3 = __hfma2(ww, *reinterpret_cast<__half2*>(&hv.w), ha3);
            }
            float2 t;
            t = __half22float2(ha0); f0 += t.x; f1 += t.y;
            t = __half22float2(ha1); f2 += t.x; f3 += t.y;
            t = __half22float2(ha2); f4 += t.x; f5 += t.y;
            t = __half22float2(ha3); f6 += t.x; f7 += t.y;
        }
        if (q < nq) {                  // <=3 leftover quads: <=3 fp16 adds per partial
            __half2 ha0 = __float2half2_rn(0.f), ha1 = ha0, ha2 = ha0, ha3 = ha0;
            for (; q < nq; q++) {
                unsigned e = eb[q * 4];
                __half2 ww = dup_hi(e);
                uint4 hv = *(const uint4*)(hlane + (size_t)(e & 0xFFFFu) * 128);
                ha0 = __hfma2(ww, *reinterpret_cast<__half2*>(&hv.x), ha0);
                ha1 = __hfma2(ww, *reinterpret_cast<__half2*>(&hv.y), ha1);
                ha2 = __hfma2(ww, *reinterpret_cast<__half2*>(&hv.z), ha2);
                ha3 = __hfma2(ww, *reinterpret_cast<__half2*>(&hv.w), ha3);
            }
            float2 t;
            t = __half22float2(ha0); f0 += t.x; f1 += t.y;
            t = __half22float2(ha1); f2 += t.x; f3 += t.y;
            t = __half22float2(ha2); f4 += t.x; f5 += t.y;
            t = __half22float2(ha3); f6 += t.x; f7 += t.y;
        }

        // merge the 4 edge-subsets (lanes chunk, chunk+8, chunk+16, chunk+24)
        #pragma unroll
        for (int o = 8; o <= 16; o <<= 1) {
            f0 += __shfl_xor_sync(0xffffffffu, f0, o);
            f1 += __shfl_xor_sync(0xffffffffu, f1, o);
            f2 += __shfl_xor_sync(0xffffffffu, f2, o);
            f3 += __shfl_xor_sync(0xffffffffu, f3, o);
            f4 += __shfl_xor_sync(0xffffffffu, f4, o);
            f5 += __shfl_xor_sync(0xffffffffu, f5, o);
            f6 += __shfl_xor_sync(0xffffffffu, f6, o);
            f7 += __shfl_xor_sync(0xffffffffu, f7, o);
        }
        // L2 norm: octet lanes 0..7 hold the 8 distinct dim-chunks
        float ss = f0*f0 + f1*f1 + f2*f2 + f3*f3 + f4*f4 + f5*f5 + f6*f6 + f7*f7;
        #pragma unroll
        for (int o = 1; o <= 4; o <<= 1) ss += __shfl_xor_sync(0xffffffffu, ss, o);
        float scale = 1.0f / fmaxf(sqrtf(ss), 1e-12f);
        f0 *= scale; f1 *= scale; f2 *= scale; f3 *= scale;
        f4 *= scale; f5 *= scale; f6 *= scale; f7 *= scale;

        if (lane < 8) {
            if (LAST) {
                float4* orow = (float4*)(fout + (size_t)wid * DD);
                orow[chunk * 2]     = make_float4(f0, f1, f2, f3);
                orow[chunk * 2 + 1] = make_float4(f4, f5, f6, f7);
            } else {
                uint4 pk;
                pk.x = h2_bits(__floats2half2_rn(f0, f1));
                pk.y = h2_bits(__floats2half2_rn(f2, f3));
                pk.z = h2_bits(__floats2half2_rn(f4, f5));
                pk.w = h2_bits(__floats2half2_rn(f6, f7));
                ((uint4*)(hout + (size_t)wid * 32))[chunk] = pk;
            }
        }
    }
}

extern "C" void kernel_launch(void* const* d_in, const int* in_sizes, int n_in,
                              void* d_out, int out_size) {
    const float* logits = (const float*)d_in[0];
    const float* h0     = (const float*)d_in[1];
    const int*   vind   = (const int*)d_in[2];
    float*       out    = (float*)d_out;

    void* sym = nullptr;
    cudaGetSymbolAddress(&sym, g_hh);
    __half2* buf0 = (__half2*)sym;
    __half2* buf1 = buf0 + (size_t)ROWS * 32;

    const int TPB = 256;
    const int warpBlocks = (ROWS * 32) / TPB;   // 4096 blocks, warp per row

    k_fused<<<warpBlocks, TPB>>>(h0, logits, vind);
    k_pad<<<(ROWS + TPB - 1) / TPB, TPB>>>();

    for (int it = 0; it < NITER; it++) {
        const __half2* in = (it & 1) ? buf1 : buf0;
        __half2* o = (it & 1) ? buf0 : buf1;
        if (it == NITER - 1)
            k_prop<true><<<PROP_BLOCKS, TPB>>>(in, o, out, it);
        else
            k_prop<false><<<PROP_BLOCKS, TPB>>>(in, o, nullptr, it);
    }
}

// round 15
// speedup vs baseline: 1.5052x; 1.5052x over previous
#include <cuda_runtime.h>
#include <cuda_fp16.h>

#define BB 2
#define NN 16384
#define KT 58
#define DD 64
#define ROWS (BB*NN)          // 32768
#define NITER 10
#define STRIDE 160            // padded slots per destination row

// ---- static device scratch (no runtime allocs; zero-initialized at load) ----
__device__ __half2  g_hh[2][ROWS * 32];       // ping-pong h, fp16, 4 MB each
__device__ int      g_cnt[ROWS];              // fill cursor; ALWAYS left zeroed by k_pad
__device__ int      g_deg[ROWS];              // padded degree consumed by k_prop
__device__ unsigned g_edges[ROWS * STRIDE];   // packed {src:16 | fp16(w):16}, 21 MB

static __device__ __forceinline__ unsigned h2_bits(__half2 h) {
    return *reinterpret_cast<unsigned*>(&h);
}
// duplicate the high 16 bits (fp16 weight) into both halves -> half2(w, w)
static __device__ __forceinline__ __half2 dup_hi(unsigned e) {
    unsigned d;
    asm("prmt.b32 %0, %1, %1, 0x3232;" : "=r"(d) : "r"(e));
    return *reinterpret_cast<__half2*>(&d);
}

// Fused prologue: per-row softmax(h0) -> g_hh[0], and adjacency+transposed fill.
// Relies on g_cnt == 0 on entry (static init on first run; k_pad re-zeroes after).
__global__ void k_fused(const float* __restrict__ h0,
                        const float* __restrict__ logits,
                        const int*   __restrict__ vind) {
    int wid  = (blockIdx.x * blockDim.x + threadIdx.x) >> 5;
    int lane = threadIdx.x & 31;
    if (wid >= ROWS) return;

    // ---- part 1: h = softmax(h0) over D=64, stored fp16 ----
    {
        const float2* r = (const float2*)(h0 + (size_t)wid * DD);
        float2 v = r[lane];
        float m = fmaxf(v.x, v.y);
        #pragma unroll
        for (int o = 16; o; o >>= 1) m = fmaxf(m, __shfl_xor_sync(0xffffffffu, m, o));
        float ea = __expf(v.x - m), eb = __expf(v.y - m);
        float s = ea + eb;
        #pragma unroll
        for (int o = 16; o; o >>= 1) s += __shfl_xor_sync(0xffffffffu, s, o);
        float inv = 1.0f / s;
        g_hh[0][(size_t)wid * 32 + lane] = __floats2half2_rn(ea * inv, eb * inv);
    }

    // ---- part 2: w = exp(l - rowmax) (== softmax/max(softmax)); transposed fill ----
    const float* r = logits + (size_t)wid * KT;
    float a = r[lane];
    float b = (lane < KT - 32) ? r[lane + 32] : -3.0e38f;
    float m = fmaxf(a, b);
    #pragma unroll
    for (int o = 16; o; o >>= 1) m = fmaxf(m, __shfl_xor_sync(0xffffffffu, m, o));
    int batch = wid / NN;
    int u     = wid - batch * NN;
    const int* vr = vind + (size_t)wid * KT;
    {
        int v = vr[lane];
        if ((unsigned)v < NN) {
            int gv = batch * NN + v;
            int p = atomicAdd(&g_cnt[gv], 1);
            unsigned wb = (unsigned)__half_as_ushort(__float2half_rn(__expf(a - m)));
            if (p < STRIDE)
                g_edges[(size_t)gv * STRIDE + p] = (unsigned)u | (wb << 16);
        }
    }
    if (lane < KT - 32) {
        int v = vr[lane + 32];
        if ((unsigned)v < NN) {
            int gv = batch * NN + v;
            int p = atomicAdd(&g_cnt[gv], 1);
            unsigned wb = (unsigned)__half_as_ushort(__float2half_rn(__expf(b - m)));
            if (p < STRIDE)
                g_edges[(size_t)gv * STRIDE + p] = (unsigned)u | (wb << 16);
        }
    }
}

// Pad each row's edge list to a multiple of 4 with zero edges, publish padded degree
// to g_deg, and re-zero g_cnt so the next run (graph replay) starts clean.
__global__ void k_pad() {
    int i = blockIdx.x * blockDim.x + threadIdx.x;
    if (i >= ROWS) return;
    int c = g_cnt[i];
    if (c > STRIDE) c = STRIDE;
    int np = (c + 3) & ~3;
    unsigned* e = g_edges + (size_t)i * STRIDE;
    for (int p = c; p < np; p++) e[p] = 0u;
    g_deg[i] = np;
    g_cnt[i] = 0;
}

// One propagation step: out[v] = L2norm( sum_e w_e * h[u_e] ).
// Static warp-per-row (work-stealing measured 1.46x SLOWER: ATOMG+SHFL grab latency
// sits serially between rows). TPB=64 -> block tail is max-of-2 Poisson rows, not
// max-of-8, while reg budget stays 42 (no spill; loop needs 40).
// Per row: 8 lanes per edge (octet = lane>>3 picks edge q*4+oct), lane covers 8 dims
// [(lane&7)*8..+8) via one 16B LDG.128 + 4 HFMA2. 16 edges per fp32 spill.
template <bool LAST>
__global__ void __launch_bounds__(64, 24)
k_prop(const __half2* __restrict__ hin, __half2* __restrict__ hout,
       float* __restrict__ fout) {
    int wid  = (blockIdx.x * blockDim.x + threadIdx.x) >> 5;
    int lane = threadIdx.x & 31;
    if (wid >= ROWS) return;
    int batch = wid / NN;
    int oct   = lane >> 3;     // which of 4 concurrent edges in a quad
    int chunk = lane & 7;      // which 16B slice of the 128B h row

    const char*     hlane = (const char*)(hin + (size_t)batch * NN * 32) + chunk * 16;
    const unsigned* eb    = g_edges + (size_t)wid * STRIDE + oct;

    int nq  = g_deg[wid] >> 2;     // quads (degree is a multiple of 4)
    int nq4 = nq & ~3;             // full 16-edge super-groups

    float f0 = 0.f, f1 = 0.f, f2 = 0.f, f3 = 0.f, f4 = 0.f, f5 = 0.f, f6 = 0.f, f7 = 0.f;

    int q = 0;
    for (; q < nq4; q += 4) {
        __half2 ha0 = __float2half2_rn(0.f), ha1 = ha0, ha2 = ha0, ha3 = ha0;
        #pragma unroll
        for (int k = 0; k < 4; k++) {
            unsigned e = eb[(q + k) * 4];
            __half2 ww = dup_hi(e);
            uint4 hv = *(const uint4*)(hlane + (size_t)(e & 0xFFFFu) * 128);
            ha0 = __hfma2(ww, *reinterpret_cast<__half2*>(&hv.x), ha0);
            ha1 = __hfma2(ww, *reinterpret_cast<__half2*>(&hv.y), ha1);
            ha2 = __hfma2(ww, *reinterpret_cast<__half2*>(&hv.z), ha2);
            ha3 = __hfma2(ww, *reinterpret_cast<__half2*>(&hv.w), ha3);
        }
        float2 t;
        t = __half22float2(ha0); f0 += t.x; f1 += t.y;
        t = __half22float2(ha1); f2 += t.x; f3 += t.y;
        t = __half22float2(ha2); f4 += t.x; f5 += t.y;
        t = __half22float2(ha3); f6 += t.x; f7 += t.y;
    }
    if (q < nq) {                  // <=3 leftover quads: <=3 fp16 adds per partial
        __half2 ha0 = __float2half2_rn(0.f), ha1 = ha0, ha2 = ha0, ha3 = ha0;
        for (; q < nq; q++) {
            unsigned e = eb[q * 4];
            __half2 ww = dup_hi(e);
            uint4 hv = *(const uint4*)(hlane + (size_t)(e & 0xFFFFu) * 128);
            ha0 = __hfma2(ww, *reinterpret_cast<__half2*>(&hv.x), ha0);
            ha1 = __hfma2(ww, *reinterpret_cast<__half2*>(&hv.y), ha1);
            ha2 = __hfma2(ww, *reinterpret_cast<__half2*>(&hv.z), ha2);
            ha3 = __hfma2(ww, *reinterpret_cast<__half2*>(&hv.w), ha3);
        }
        float2 t;
        t = __half22float2(ha0); f0 += t.x; f1 += t.y;
        t = __half22float2(ha1); f2 += t.x; f3 += t.y;
        t = __half22float2(ha2); f4 += t.x; f5 += t.y;
        t = __half22float2(ha3); f6 += t.x; f7 += t.y;
    }

    // merge the 4 edge-subsets (lanes chunk, chunk+8, chunk+16, chunk+24)
    #pragma unroll
    for (int o = 8; o <= 16; o <<= 1) {
        f0 += __shfl_xor_sync(0xffffffffu, f0, o);
        f1 += __shfl_xor_sync(0xffffffffu, f1, o);
        f2 += __shfl_xor_sync(0xffffffffu, f2, o);
        f3 += __shfl_xor_sync(0xffffffffu, f3, o);
        f4 += __shfl_xor_sync(0xffffffffu, f4, o);
        f5 += __shfl_xor_sync(0xffffffffu, f5, o);
        f6 += __shfl_xor_sync(0xffffffffu, f6, o);
        f7 += __shfl_xor_sync(0xffffffffu, f7, o);
    }
    // L2 norm: octet lanes 0..7 hold the 8 distinct dim-chunks
    float ss = f0*f0 + f1*f1 + f2*f2 + f3*f3 + f4*f4 + f5*f5 + f6*f6 + f7*f7;
    #pragma unroll
    for (int o = 1; o <= 4; o <<= 1) ss += __shfl_xor_sync(0xffffffffu, ss, o);
    float scale = 1.0f / fmaxf(sqrtf(ss), 1e-12f);
    f0 *= scale; f1 *= scale; f2 *= scale; f3 *= scale;
    f4 *= scale; f5 *= scale; f6 *= scale; f7 *= scale;

    if (lane < 8) {
        if (LAST) {
            float4* orow = (float4*)(fout + (size_t)wid * DD);
            orow[chunk * 2]     = make_float4(f0, f1, f2, f3);
            orow[chunk * 2 + 1] = make_float4(f4, f5, f6, f7);
        } else {
            uint4 pk;
            pk.x = h2_bits(__floats2half2_rn(f0, f1));
            pk.y = h2_bits(__floats2half2_rn(f2, f3));
            pk.z = h2_bits(__floats2half2_rn(f4, f5));
            pk.w = h2_bits(__floats2half2_rn(f6, f7));
            ((uint4*)(hout + (size_t)wid * 32))[chunk] = pk;
        }
    }
}

extern "C" void kernel_launch(void* const* d_in, const int* in_sizes, int n_in,
                              void* d_out, int out_size) {
    const float* logits = (const float*)d_in[0];
    const float* h0     = (const float*)d_in[1];
    const int*   vind   = (const int*)d_in[2];
    float*       out    = (float*)d_out;

    void* sym = nullptr;
    cudaGetSymbolAddress(&sym, g_hh);
    __half2* buf0 = (__half2*)sym;
    __half2* buf1 = buf0 + (size_t)ROWS * 32;

    const int TPB = 256;
    const int warpBlocks = (ROWS * 32) / TPB;   // 4096 blocks, warp per row

    k_fused<<<warpBlocks, TPB>>>(h0, logits, vind);
    k_pad<<<(ROWS + TPB - 1) / TPB, TPB>>>();

    const int PROP_TPB    = 64;                         // 2 warps: max-of-2 block tail
    const int propBlocks  = (ROWS * 32) / PROP_TPB;     // 16384 blocks

    for (int it = 0; it < NITER; it++) {
        const __half2* in = (it & 1) ? buf1 : buf0;
        __half2* o = (it & 1) ? buf0 : buf1;
        if (it == NITER - 1)
            k_prop<true><<<propBlocks, PROP_TPB>>>(in, o, out);
        else
            k_prop<false><<<propBlocks, PROP_TPB>>>(in, o, nullptr);
    }
}

// round 16
// speedup vs baseline: 1.6417x; 1.0906x over previous
#include <cuda_runtime.h>
#include <cuda_fp16.h>

#define BB 2
#define NN 16384
#define KT 58
#define DD 64
#define ROWS (BB*NN)          // 32768
#define NITER 10
#define STRIDE 160            // padded slots per destination row

// ---- static device scratch (no runtime allocs; zero-initialized at load) ----
__device__ __half2  g_hh[2][ROWS * 32];       // ping-pong h, fp16, 4 MB each
__device__ int      g_cnt[ROWS];              // fill cursor; ALWAYS left zeroed by k_pad
__device__ int      g_deg[ROWS];              // padded degree consumed by k_prop
__device__ unsigned g_edges[ROWS * STRIDE];   // packed {src:16 | fp16(w):16}, 21 MB

static __device__ __forceinline__ unsigned h2_bits(__half2 h) {
    return *reinterpret_cast<unsigned*>(&h);
}
// duplicate the high 16 bits (fp16 weight) into both halves -> half2(w, w)
static __device__ __forceinline__ __half2 dup_hi(unsigned e) {
    unsigned d;
    asm("prmt.b32 %0, %1, %1, 0x3232;" : "=r"(d) : "r"(e));
    return *reinterpret_cast<__half2*>(&d);
}

// Fused prologue: per-row softmax(h0) -> g_hh[0], and adjacency+transposed fill.
// Relies on g_cnt == 0 on entry (static init on first run; k_pad re-zeroes after).
__global__ void k_fused(const float* __restrict__ h0,
                        const float* __restrict__ logits,
                        const int*   __restrict__ vind) {
    int wid  = (blockIdx.x * blockDim.x + threadIdx.x) >> 5;
    int lane = threadIdx.x & 31;
    if (wid >= ROWS) return;

    // ---- part 1: h = softmax(h0) over D=64, stored fp16 ----
    {
        const float2* r = (const float2*)(h0 + (size_t)wid * DD);
        float2 v = r[lane];
        float m = fmaxf(v.x, v.y);
        #pragma unroll
        for (int o = 16; o; o >>= 1) m = fmaxf(m, __shfl_xor_sync(0xffffffffu, m, o));
        float ea = __expf(v.x - m), eb = __expf(v.y - m);
        float s = ea + eb;
        #pragma unroll
        for (int o = 16; o; o >>= 1) s += __shfl_xor_sync(0xffffffffu, s, o);
        float inv = 1.0f / s;
        g_hh[0][(size_t)wid * 32 + lane] = __floats2half2_rn(ea * inv, eb * inv);
    }

    // ---- part 2: w = exp(l - rowmax) (== softmax/max(softmax)); transposed fill ----
    const float* r = logits + (size_t)wid * KT;
    float a = r[lane];
    float b = (lane < KT - 32) ? r[lane + 32] : -3.0e38f;
    float m = fmaxf(a, b);
    #pragma unroll
    for (int o = 16; o; o >>= 1) m = fmaxf(m, __shfl_xor_sync(0xffffffffu, m, o));
    int batch = wid / NN;
    int u     = wid - batch * NN;
    const int* vr = vind + (size_t)wid * KT;
    {
        int v = vr[lane];
        if ((unsigned)v < NN) {
            int gv = batch * NN + v;
            int p = atomicAdd(&g_cnt[gv], 1);
            unsigned wb = (unsigned)__half_as_ushort(__float2half_rn(__expf(a - m)));
            if (p < STRIDE)
                g_edges[(size_t)gv * STRIDE + p] = (unsigned)u | (wb << 16);
        }
    }
    if (lane < KT - 32) {
        int v = vr[lane + 32];
        if ((unsigned)v < NN) {
            int gv = batch * NN + v;
            int p = atomicAdd(&g_cnt[gv], 1);
            unsigned wb = (unsigned)__half_as_ushort(__float2half_rn(__expf(b - m)));
            if (p < STRIDE)
                g_edges[(size_t)gv * STRIDE + p] = (unsigned)u | (wb << 16);
        }
    }
}

// Pad each row's edge list to a multiple of 4 with zero edges, publish padded degree
// to g_deg, and re-zero g_cnt so the next run (graph replay) starts clean.
__global__ void k_pad() {
    int i = blockIdx.x * blockDim.x + threadIdx.x;
    if (i >= ROWS) return;
    int c = g_cnt[i];
    if (c > STRIDE) c = STRIDE;
    int np = (c + 3) & ~3;
    unsigned* e = g_edges + (size_t)i * STRIDE;
    for (int p = c; p < np; p++) e[p] = 0u;
    g_deg[i] = np;
    g_cnt[i] = 0;
}

// One propagation step: out[v] = L2norm( sum_e w_e * h[u_e] ).
// Static warp-per-row, TPB=64 (max-of-2 block tail). Edge loads for super-group
// g+1 are prefetched into registers before group g's h-loads/FMAs, breaking the
// serial edge->h L2 round-trip chain. launch_bounds (64,20) = 48-reg budget;
// (64,24)'s 42-reg budget can't hold the prefetch set (R12: reg squeeze => MLP
// collapse, 1.4x slower). Per row: 8 lanes/edge, lane covers 8 dims via one
// LDG.128 + 4 HFMA2; 16 edges per fp32 spill.
template <bool LAST>
__global__ void __launch_bounds__(64, 20)
k_prop(const __half2* __restrict__ hin, __half2* __restrict__ hout,
       float* __restrict__ fout) {
    int wid  = (blockIdx.x * blockDim.x + threadIdx.x) >> 5;
    int lane = threadIdx.x & 31;
    if (wid >= ROWS) return;
    int batch = wid / NN;
    int oct   = lane >> 3;     // which of 4 concurrent edges in a quad
    int chunk = lane & 7;      // which 16B slice of the 128B h row

    const char*     hlane = (const char*)(hin + (size_t)batch * NN * 32) + chunk * 16;
    const unsigned* eb    = g_edges + (size_t)wid * STRIDE + oct;

    int nq  = g_deg[wid] >> 2;     // quads (degree is a multiple of 4)
    int nq4 = nq & ~3;             // full 16-edge super-groups

    float f0 = 0.f, f1 = 0.f, f2 = 0.f, f3 = 0.f, f4 = 0.f, f5 = 0.f, f6 = 0.f, f7 = 0.f;

    // prefetch first super-group's 4 edge words
    unsigned p0 = 0, p1 = 0, p2 = 0, p3 = 0;
    if (nq4 > 0) {
        p0 = eb[0]; p1 = eb[4]; p2 = eb[8]; p3 = eb[12];
    }

    for (int q = 0; q < nq4; q += 4) {
        unsigned e0 = p0, e1 = p1, e2 = p2, e3 = p3;
        int qn = q + 4;
        if (qn < nq4) {        // prefetch next group while this group's h-loads fly
            p0 = eb[qn * 4]; p1 = eb[qn * 4 + 4]; p2 = eb[qn * 4 + 8]; p3 = eb[qn * 4 + 12];
        }
        // issue all 4 h-loads up front (independent, MLP=4)
        uint4 h0v = *(const uint4*)(hlane + (size_t)(e0 & 0xFFFFu) * 128);
        uint4 h1v = *(const uint4*)(hlane + (size_t)(e1 & 0xFFFFu) * 128);
        uint4 h2v = *(const uint4*)(hlane + (size_t)(e2 & 0xFFFFu) * 128);
        uint4 h3v = *(const uint4*)(hlane + (size_t)(e3 & 0xFFFFu) * 128);
        __half2 w0 = dup_hi(e0), w1 = dup_hi(e1), w2 = dup_hi(e2), w3 = dup_hi(e3);

        __half2 ha0, ha1, ha2, ha3;
        ha0 = __hmul2(w0, *reinterpret_cast<__half2*>(&h0v.x));
        ha1 = __hmul2(w0, *reinterpret_cast<__half2*>(&h0v.y));
        ha2 = __hmul2(w0, *reinterpret_cast<__half2*>(&h0v.z));
        ha3 = __hmul2(w0, *reinterpret_cast<__half2*>(&h0v.w));
        ha0 = __hfma2(w1, *reinterpret_cast<__half2*>(&h1v.x), ha0);
        ha1 = __hfma2(w1, *reinterpret_cast<__half2*>(&h1v.y), ha1);
        ha2 = __hfma2(w1, *reinterpret_cast<__half2*>(&h1v.z), ha2);
        ha3 = __hfma2(w1, *reinterpret_cast<__half2*>(&h1v.w), ha3);
        ha0 = __hfma2(w2, *reinterpret_cast<__half2*>(&h2v.x), ha0);
        ha1 = __hfma2(w2, *reinterpret_cast<__half2*>(&h2v.y), ha1);
        ha2 = __hfma2(w2, *reinterpret_cast<__half2*>(&h2v.z), ha2);
        ha3 = __hfma2(w2, *reinterpret_cast<__half2*>(&h2v.w), ha3);
        ha0 = __hfma2(w3, *reinterpret_cast<__half2*>(&h3v.x), ha0);
        ha1 = __hfma2(w3, *reinterpret_cast<__half2*>(&h3v.y), ha1);
        ha2 = __hfma2(w3, *reinterpret_cast<__half2*>(&h3v.z), ha2);
        ha3 = __hfma2(w3, *reinterpret_cast<__half2*>(&h3v.w), ha3);

        float2 t;
        t = __half22float2(ha0); f0 += t.x; f1 += t.y;
        t = __half22float2(ha1); f2 += t.x; f3 += t.y;
        t = __half22float2(ha2); f4 += t.x; f5 += t.y;
        t = __half22float2(ha3); f6 += t.x; f7 += t.y;
    }
    if (nq4 < nq) {                // <=3 leftover quads: <=3 fp16 adds per partial
        __half2 ha0 = __float2half2_rn(0.f), ha1 = ha0, ha2 = ha0, ha3 = ha0;
        for (int q = nq4; q < nq; q++) {
            unsigned e = eb[q * 4];
            __half2 ww = dup_hi(e);
            uint4 hv = *(const uint4*)(hlane + (size_t)(e & 0xFFFFu) * 128);
            ha0 = __hfma2(ww, *reinterpret_cast<__half2*>(&hv.x), ha0);
            ha1 = __hfma2(ww, *reinterpret_cast<__half2*>(&hv.y), ha1);
            ha2 = __hfma2(ww, *reinterpret_cast<__half2*>(&hv.z), ha2);
            ha3 = __hfma2(ww, *reinterpret_cast<__half2*>(&hv.w), ha3);
        }
        float2 t;
        t = __half22float2(ha0); f0 += t.x; f1 += t.y;
        t = __half22float2(ha1); f2 += t.x; f3 += t.y;
        t = __half22float2(ha2); f4 += t.x; f5 += t.y;
        t = __half22float2(ha3); f6 += t.x; f7 += t.y;
    }

    // merge the 4 edge-subsets (lanes chunk, chunk+8, chunk+16, chunk+24)
    #pragma unroll
    for (int o = 8; o <= 16; o <<= 1) {
        f0 += __shfl_xor_sync(0xffffffffu, f0, o);
        f1 += __shfl_xor_sync(0xffffffffu, f1, o);
        f2 += __shfl_xor_sync(0xffffffffu, f2, o);
        f3 += __shfl_xor_sync(0xffffffffu, f3, o);
        f4 += __shfl_xor_sync(0xffffffffu, f4, o);
        f5 += __shfl_xor_sync(0xffffffffu, f5, o);
        f6 += __shfl_xor_sync(0xffffffffu, f6, o);
        f7 += __shfl_xor_sync(0xffffffffu, f7, o);
    }
    // L2 norm: octet lanes 0..7 hold the 8 distinct dim-chunks
    float ss = f0*f0 + f1*f1 + f2*f2 + f3*f3 + f4*f4 + f5*f5 + f6*f6 + f7*f7;
    #pragma unroll
    for (int o = 1; o <= 4; o <<= 1) ss += __shfl_xor_sync(0xffffffffu, ss, o);
    float scale = 1.0f / fmaxf(sqrtf(ss), 1e-12f);
    f0 *= scale; f1 *= scale; f2 *= scale; f3 *= scale;
    f4 *= scale; f5 *= scale; f6 *= scale; f7 *= scale;

    if (lane < 8) {
        if (LAST) {
            float4* orow = (float4*)(fout + (size_t)wid * DD);
            orow[chunk * 2]     = make_float4(f0, f1, f2, f3);
            orow[chunk * 2 + 1] = make_float4(f4, f5, f6, f7);
        } else {
            uint4 pk;
            pk.x = h2_bits(__floats2half2_rn(f0, f1));
            pk.y = h2_bits(__floats2half2_rn(f2, f3));
            pk.z = h2_bits(__floats2half2_rn(f4, f5));
            pk.w = h2_bits(__floats2half2_rn(f6, f7));
            ((uint4*)(hout + (size_t)wid * 32))[chunk] = pk;
        }
    }
}

extern "C" void kernel_launch(void* const* d_in, const int* in_sizes, int n_in,
                              void* d_out, int out_size) {
    const float* logits = (const float*)d_in[0];
    const float* h0     = (const float*)d_in[1];
    const int*   vind   = (const int*)d_in[2];
    float*       out    = (float*)d_out;

    void* sym = nullptr;
    cudaGetSymbolAddress(&sym, g_hh);
    __half2* buf0 = (__half2*)sym;
    __half2* buf1 = buf0 + (size_t)ROWS * 32;

    const int TPB = 256;
    const int warpBlocks = (ROWS * 32) / TPB;   // 4096 blocks, warp per row

    k_fused<<<warpBlocks, TPB>>>(h0, logits, vind);
    k_pad<<<(ROWS + TPB - 1) / TPB, TPB>>>();

    const int PROP_TPB    = 64;                         // 2 warps: max-of-2 block tail
    const int propBlocks  = (ROWS * 32) / PROP_TPB;     // 16384 blocks

    for (int it = 0; it < NITER; it++) {
        const __half2* in = (it & 1) ? buf1 : buf0;
        __half2* o = (it & 1) ? buf0 : buf1;
        if (it == NITER - 1)
            k_prop<true><<<propBlocks, PROP_TPB>>>(in, o, out);
        else
            k_prop<false><<<propBlocks, PROP_TPB>>>(in, o, nullptr);
    }
}